// round 1
// baseline (speedup 1.0000x reference)
#include <cuda_runtime.h>
#include <math.h>
#include <float.h>

#define NTHREADS   256
#define T_REAL     200
#define T_PAD      256
#define E_DIM      64
#define H1_DIM     64
#define H2_DIM     32
#define H2_STRIDE  33
#define MASK_VAL_F (-4294967296.0f)   // jnp.float32(-2**32+1) rounds to -2^32

__device__ __forceinline__ float warpRedMax(float v) {
    #pragma unroll
    for (int o = 16; o > 0; o >>= 1) v = fmaxf(v, __shfl_xor_sync(0xffffffffu, v, o));
    return v;
}
__device__ __forceinline__ float warpRedSum(float v) {
    #pragma unroll
    for (int o = 16; o > 0; o >>= 1) v += __shfl_xor_sync(0xffffffffu, v, o);
    return v;
}

// Shared memory layout (floats):
//   keysS : T_PAD*64   = 16384   keys tile (rows 200..255 zeroed)
//   h1S   : T_PAD*64   = 16384   layer-1 activations (reused as scratch at end)
//   h2S   : T_PAD*33   =  8448   layer-2 activations (stride 33: conflict-free row reads)
//   WqS   : 64*64      =  4096   per-batch effective layer-1 weights
//   W2S   : 64*32      =  2048
//   qS,qWbS: 64+64
//   W3S,b2S: 32+32
//   wS    : 256                  softmax weights
//   redS  : 32                   block-reduce scratch
#define SMEM_FLOATS (16384 + 16384 + 8448 + 4096 + 2048 + 64 + 64 + 32 + 32 + 256 + 32)

extern "C" __global__ void __launch_bounds__(NTHREADS, 1)
asp_kernel(const float* __restrict__ query,
           const float* __restrict__ keys,
           const int*   __restrict__ klw,     // keys_len raw 32-bit words (int32 or int64)
           const float* __restrict__ W1,
           const float* __restrict__ b1,
           const float* __restrict__ W2,
           const float* __restrict__ b2,
           const float* __restrict__ W3,
           const float* __restrict__ b3,
           float* __restrict__ out)
{
    extern __shared__ float sm[];
    float* keysS = sm;                          // 16384
    float* h1S   = keysS + T_PAD * E_DIM;       // 16384
    float* h2S   = h1S   + T_PAD * H1_DIM;      // 8448
    float* WqS   = h2S   + T_PAD * H2_STRIDE;   // 4096
    float* W2S   = WqS   + 64 * 64;             // 2048
    float* qS    = W2S   + 64 * 32;             // 64
    float* qWbS  = qS    + 64;                  // 64
    float* W3S   = qWbS  + 64;                  // 32
    float* b2S   = W3S   + 32;                  // 32
    float* wS    = b2S   + 32;                  // 256
    float* redS  = wS    + T_PAD;               // 32

    const int b   = blockIdx.x;
    const int tid = threadIdx.x;

    const float* qg = query + (size_t)b * E_DIM;
    const float* kg = keys  + (size_t)b * T_REAL * E_DIM;

    // ---- Stage small operands ----
    if (tid < 64)                qS[tid]      = qg[tid];
    else if (tid < 96)           W3S[tid-64]  = W3[tid-64];
    else if (tid < 128)          b2S[tid-96]  = b2[tid-96];
    for (int i = tid; i < 64 * 32; i += NTHREADS) W2S[i] = W2[i];
    __syncthreads();

    // ---- Per-batch effective layer-1 weight:
    //      Weff[i][j] = (W1b - W1c)[i][j] + q_i * W1d[i][j]
    for (int idx = tid; idx < 64 * 64; idx += NTHREADS) {
        const int i = idx >> 6;
        WqS[idx] = W1[64*64 + idx] - W1[128*64 + idx] + qS[i] * W1[192*64 + idx];
    }
    // qWb[j] = b1[j] + sum_i q_i * (W1a + W1c)[i][j]
    if (tid < 64) {
        float s = b1[tid];
        #pragma unroll 8
        for (int i = 0; i < 64; i++)
            s += qS[i] * (W1[i*64 + tid] + W1[(128 + i)*64 + tid]);
        qWbS[tid] = s;
    }

    // ---- Keys tile into SMEM (zero-pad rows 200..255) ----
    {
        float4* d4 = (float4*)keysS;
        const float4* s4 = (const float4*)kg;
        for (int i = tid; i < T_REAL * E_DIM / 4; i += NTHREADS) d4[i] = s4[i];
        for (int i = T_REAL * E_DIM / 4 + tid; i < T_PAD * E_DIM / 4; i += NTHREADS)
            d4[i] = make_float4(0.f, 0.f, 0.f, 0.f);
    }
    __syncthreads();

    // ---- Layer 1: h1 = relu(qWb + keys @ Weff)  [T_PAD x 64, K=64] ----
    // Thread tile: 8t x 4j.  tid = tt*16 + jt so a warp holds 2 tt-groups x 16 jt:
    // k-operand loads broadcast within 16-lane groups; Weff read as float4 rows.
    {
        const int jt = tid & 15;
        const int tt = tid >> 4;
        const int j  = jt * 4;
        const float q0 = qWbS[j], q1 = qWbS[j+1], q2 = qWbS[j+2], q3 = qWbS[j+3];
        #pragma unroll
        for (int m0 = 0; m0 < T_PAD; m0 += 128) {
            const int tb = m0 + tt * 8;
            float c[8][4];
            #pragma unroll
            for (int r = 0; r < 8; r++) { c[r][0]=q0; c[r][1]=q1; c[r][2]=q2; c[r][3]=q3; }
            #pragma unroll 4
            for (int i = 0; i < 64; i++) {
                const float4 w = *(const float4*)&WqS[i*64 + j];
                #pragma unroll
                for (int r = 0; r < 8; r++) {
                    const float a = keysS[(tb + r) * E_DIM + i];
                    c[r][0] += a * w.x; c[r][1] += a * w.y;
                    c[r][2] += a * w.z; c[r][3] += a * w.w;
                }
            }
            #pragma unroll
            for (int r = 0; r < 8; r++) {
                float4 v;
                v.x = fmaxf(c[r][0], 0.f); v.y = fmaxf(c[r][1], 0.f);
                v.z = fmaxf(c[r][2], 0.f); v.w = fmaxf(c[r][3], 0.f);
                *(float4*)&h1S[(tb + r) * H1_DIM + j] = v;
            }
        }
    }
    __syncthreads();

    // ---- Layer 2: h2 = relu(b2 + h1 @ W2)  [T_PAD x 32, K=64] ----
    {
        const int jt = tid & 7;
        const int tt = tid >> 3;          // 0..31 -> covers all 256 t in one tile
        const int j  = jt * 4;
        const int tb = tt * 8;
        float c[8][4];
        const float q0 = b2S[j], q1 = b2S[j+1], q2 = b2S[j+2], q3 = b2S[j+3];
        #pragma unroll
        for (int r = 0; r < 8; r++) { c[r][0]=q0; c[r][1]=q1; c[r][2]=q2; c[r][3]=q3; }
        #pragma unroll 4
        for (int i = 0; i < 64; i++) {
            const float4 w = *(const float4*)&W2S[i*32 + j];
            #pragma unroll
            for (int r = 0; r < 8; r++) {
                const float a = h1S[(tb + r) * H1_DIM + i];
                c[r][0] += a * w.x; c[r][1] += a * w.y;
                c[r][2] += a * w.z; c[r][3] += a * w.w;
            }
        }
        #pragma unroll
        for (int r = 0; r < 8; r++) {
            h2S[(tb + r) * H2_STRIDE + j + 0] = fmaxf(c[r][0], 0.f);
            h2S[(tb + r) * H2_STRIDE + j + 1] = fmaxf(c[r][1], 0.f);
            h2S[(tb + r) * H2_STRIDE + j + 2] = fmaxf(c[r][2], 0.f);
            h2S[(tb + r) * H2_STRIDE + j + 3] = fmaxf(c[r][3], 0.f);
        }
    }
    __syncthreads();

    // ---- keys_len: detect int64 vs int32 storage ----
    // int64 little-endian: every odd 32-bit word is a zero high-half.
    // int32 with values in [0,200): P(6 sampled words all zero) ~ 200^-6.
    int len;
    {
        const bool is64 = ((klw[1] | klw[3] | klw[5] | klw[7] | klw[9] | klw[11]) == 0);
        len = is64 ? klw[2 * b] : klw[b];
    }

    // ---- Score + mask + softmax ----
    float sc = -FLT_MAX;
    if (tid < T_REAL) {
        float s = b3[0];
        #pragma unroll 8
        for (int o = 0; o < 32; o++) s += h2S[tid * H2_STRIDE + o] * W3S[o];
        sc = (tid < len) ? s : MASK_VAL_F;
    }
    float m = warpRedMax(sc);
    if ((tid & 31) == 0) redS[tid >> 5] = m;
    __syncthreads();
    float bm = redS[0];
    #pragma unroll
    for (int w = 1; w < 8; w++) bm = fmaxf(bm, redS[w]);
    __syncthreads();                       // redS reuse
    const float e = (tid < T_REAL) ? expf(sc - bm) : 0.f;
    float s1 = warpRedSum(e);
    if ((tid & 31) == 0) redS[tid >> 5] = s1;
    __syncthreads();
    float bs = 0.f;
    #pragma unroll
    for (int w = 0; w < 8; w++) bs += redS[w];
    wS[tid] = e * (1.0f / bs);
    __syncthreads();

    // ---- Weighted sum: out[e] = sum_t w_t * keys[t][e] ----
    {
        const int e_ = tid & 63;
        const int g  = tid >> 6;
        float acc = 0.f;
        for (int t = g; t < T_REAL; t += 4)
            acc += wS[t] * keysS[t * E_DIM + e_];
        h1S[g * 64 + e_] = acc;            // h1S reused as scratch
    }
    __syncthreads();
    if (tid < 64)
        out[(size_t)b * E_DIM + tid] =
            h1S[tid] + h1S[64 + tid] + h1S[128 + tid] + h1S[192 + tid];
}

extern "C" void kernel_launch(void* const* d_in, const int* in_sizes, int n_in,
                              void* d_out, int out_size) {
    const float* query = (const float*)d_in[0];
    const float* keys  = (const float*)d_in[1];
    const int*   klen  = (const int*)  d_in[2];
    const float* W1    = (const float*)d_in[3];
    const float* b1    = (const float*)d_in[4];
    const float* W2    = (const float*)d_in[5];
    const float* b2    = (const float*)d_in[6];
    const float* W3    = (const float*)d_in[7];
    const float* b3    = (const float*)d_in[8];
    float* out = (float*)d_out;

    const int B = in_sizes[0] / E_DIM;                // query is (B,1,64)
    const size_t smem_bytes = (size_t)SMEM_FLOATS * sizeof(float);  // ~191 KB

    cudaFuncSetAttribute(asp_kernel,
                         cudaFuncAttributeMaxDynamicSharedMemorySize,
                         (int)smem_bytes);

    asp_kernel<<<B, NTHREADS, smem_bytes>>>(query, keys, klen,
                                            W1, b1, W2, b2, W3, b3, out);
}

// round 2
// speedup vs baseline: 1.4770x; 1.4770x over previous
#include <cuda_runtime.h>
#include <math.h>
#include <float.h>

#define NTHREADS   256
#define T_REAL     200
#define T_PAD      256
#define TILE_T     128
#define E_DIM      64
#define H1_STRIDE  65
#define MASK_VAL_F (-4294967296.0f)   // jnp.float32(-2**32+1) rounds to -2^32

__device__ __forceinline__ float warpRedMax(float v) {
    #pragma unroll
    for (int o = 16; o > 0; o >>= 1) v = fmaxf(v, __shfl_xor_sync(0xffffffffu, v, o));
    return v;
}
__device__ __forceinline__ float warpRedSum(float v) {
    #pragma unroll
    for (int o = 16; o > 0; o >>= 1) v += __shfl_xor_sync(0xffffffffu, v, o);
    return v;
}

// Shared memory (floats), ~90.4 KB total -> 2 CTAs/SM:
//   keysT : 128*64   = 8192   one 128-row keys tile
//   h1S   : 128*65   = 8320   layer-1 tile (stride 65: conflict-free L2 reads)
//   WqS   : 64*64    = 4096   per-batch effective layer-1 weights
//   W2S   : 64*32    = 2048
//   qS,qWbS: 64+64   W3S,b2S: 32+32
//   wS    : 256      scores -> softmax weights
//   redS  : 32
#define SMEM_FLOATS (8192 + 8320 + 4096 + 2048 + 64 + 64 + 32 + 32 + 256 + 32)

extern "C" __global__ void __launch_bounds__(NTHREADS, 2)
asp_kernel(const float* __restrict__ query,
           const float* __restrict__ keys,
           const int*   __restrict__ klw,     // keys_len raw 32-bit words (int32 or int64)
           const float* __restrict__ W1,
           const float* __restrict__ b1,
           const float* __restrict__ W2,
           const float* __restrict__ b2,
           const float* __restrict__ W3,
           const float* __restrict__ b3,
           float* __restrict__ out)
{
    extern __shared__ float sm[];
    float* keysT = sm;                            // 8192
    float* h1S   = keysT + TILE_T * E_DIM;        // 8320
    float* WqS   = h1S   + TILE_T * H1_STRIDE;    // 4096
    float* W2S   = WqS   + 64 * 64;               // 2048
    float* qS    = W2S   + 64 * 32;               // 64
    float* qWbS  = qS    + 64;                    // 64
    float* W3S   = qWbS  + 64;                    // 32
    float* b2S   = W3S   + 32;                    // 32
    float* wS    = b2S   + 32;                    // 256
    float* redS  = wS    + T_PAD;                 // 32

    const int b   = blockIdx.x;
    const int tid = threadIdx.x;

    const float* qg = query + (size_t)b * E_DIM;
    const float* kg = keys  + (size_t)b * T_REAL * E_DIM;

    // ---- keys_len: detect int64 vs int32 storage ----
    int len;
    {
        const bool is64 = ((klw[1] | klw[3] | klw[5] | klw[7] | klw[9] | klw[11]) == 0);
        len = is64 ? klw[2 * b] : klw[b];
    }
    const float b3v = b3[0];

    // ---- Stage small operands ----
    if (tid < 64)                qS[tid]      = qg[tid];
    else if (tid < 96)           W3S[tid-64]  = W3[tid-64];
    else if (tid < 128)          b2S[tid-96]  = b2[tid-96];
    for (int i = tid; i < 64 * 32; i += NTHREADS) W2S[i] = W2[i];
    __syncthreads();

    // ---- Per-batch effective layer-1 weight:
    //      Weff[i][j] = (W1b - W1c)[i][j] + q_i * W1d[i][j]
    for (int idx = tid; idx < 64 * 64; idx += NTHREADS) {
        const int i = idx >> 6;
        WqS[idx] = W1[64*64 + idx] - W1[128*64 + idx] + qS[i] * W1[192*64 + idx];
    }
    // qWb[j] = b1[j] + sum_i q_i * (W1a + W1c)[i][j]
    if (tid < 64) {
        float s = b1[tid];
        #pragma unroll 8
        for (int i = 0; i < 64; i++)
            s += qS[i] * (W1[i*64 + tid] + W1[(128 + i)*64 + tid]);
        qWbS[tid] = s;
    }
    __syncthreads();

    // ================= Two 128-row tiles over T =================
    #pragma unroll 1
    for (int tile = 0; tile < 2; tile++) {
        const int rowBase = tile * TILE_T;

        // ---- keys tile -> SMEM (zero-pad rows >= 200) ----
        {
            const int realRows  = (tile == 0) ? TILE_T : (T_REAL - TILE_T);  // 128 / 72
            const int realWords = realRows * E_DIM / 4;
            float4* d4 = (float4*)keysT;
            const float4* s4 = (const float4*)(kg + rowBase * E_DIM);
            for (int i = tid; i < realWords; i += NTHREADS) d4[i] = s4[i];
            for (int i = realWords + tid; i < TILE_T * E_DIM / 4; i += NTHREADS)
                d4[i] = make_float4(0.f, 0.f, 0.f, 0.f);
        }
        __syncthreads();

        // ---- Layer 1: h1 = relu(qWb + keysT @ Weff)  [128 x 64, K=64] ----
        {
            const int jt = tid & 15;
            const int tt = tid >> 4;          // 0..15, 8 rows each
            const int j  = jt * 4;
            const int tb = tt * 8;
            float c[8][4];
            {
                const float q0 = qWbS[j], q1 = qWbS[j+1], q2 = qWbS[j+2], q3 = qWbS[j+3];
                #pragma unroll
                for (int r = 0; r < 8; r++) { c[r][0]=q0; c[r][1]=q1; c[r][2]=q2; c[r][3]=q3; }
            }
            #pragma unroll 4
            for (int i = 0; i < 64; i++) {
                const float4 w = *(const float4*)&WqS[i*64 + j];
                #pragma unroll
                for (int r = 0; r < 8; r++) {
                    const float a = keysT[(tb + r) * E_DIM + i];
                    c[r][0] += a * w.x; c[r][1] += a * w.y;
                    c[r][2] += a * w.z; c[r][3] += a * w.w;
                }
            }
            #pragma unroll
            for (int r = 0; r < 8; r++) {
                float* row = &h1S[(tb + r) * H1_STRIDE + j];
                row[0] = fmaxf(c[r][0], 0.f);
                row[1] = fmaxf(c[r][1], 0.f);
                row[2] = fmaxf(c[r][2], 0.f);
                row[3] = fmaxf(c[r][3], 0.f);
            }
        }
        __syncthreads();

        // ---- Layer 2 + Layer 3 fused:
        //      h2 = relu(b2 + h1 @ W2); score = h2 . W3 + b3  ----
        {
            const int jt = tid & 7;           // 8 col-groups x 4 cols = 32
            const int tt = tid >> 3;          // 0..31, 4 rows each
            const int j  = jt * 4;
            const int tb = tt * 4;
            float c[4][4];
            {
                const float q0 = b2S[j], q1 = b2S[j+1], q2 = b2S[j+2], q3 = b2S[j+3];
                #pragma unroll
                for (int r = 0; r < 4; r++) { c[r][0]=q0; c[r][1]=q1; c[r][2]=q2; c[r][3]=q3; }
            }
            #pragma unroll 4
            for (int i = 0; i < 64; i++) {
                const float4 w = *(const float4*)&W2S[i*32 + j];
                #pragma unroll
                for (int r = 0; r < 4; r++) {
                    const float a = h1S[(tb + r) * H1_STRIDE + i];
                    c[r][0] += a * w.x; c[r][1] += a * w.y;
                    c[r][2] += a * w.z; c[r][3] += a * w.w;
                }
            }
            const float4 w3 = *(const float4*)&W3S[j];
            float sp[4];
            #pragma unroll
            for (int r = 0; r < 4; r++) {
                sp[r] = fmaxf(c[r][0], 0.f) * w3.x + fmaxf(c[r][1], 0.f) * w3.y
                      + fmaxf(c[r][2], 0.f) * w3.z + fmaxf(c[r][3], 0.f) * w3.w;
            }
            // reduce partial scores across the 8 jt lanes (consecutive in warp)
            #pragma unroll
            for (int o = 1; o < 8; o <<= 1) {
                #pragma unroll
                for (int r = 0; r < 4; r++)
                    sp[r] += __shfl_xor_sync(0xffffffffu, sp[r], o);
            }
            if (jt == 0) {
                #pragma unroll
                for (int r = 0; r < 4; r++)
                    wS[rowBase + tb + r] = sp[r] + b3v;
            }
        }
        __syncthreads();
    }

    // ---- Mask + softmax over wS ----
    float sc;
    if (tid < T_REAL) sc = (tid < len) ? wS[tid] : MASK_VAL_F;
    else              sc = -FLT_MAX;

    float m = warpRedMax(sc);
    if ((tid & 31) == 0) redS[tid >> 5] = m;
    __syncthreads();
    float bm = redS[0];
    #pragma unroll
    for (int w = 1; w < 8; w++) bm = fmaxf(bm, redS[w]);
    __syncthreads();                       // redS reuse
    const float e = (tid < T_REAL) ? expf(sc - bm) : 0.f;
    float s1 = warpRedSum(e);
    if ((tid & 31) == 0) redS[tid >> 5] = s1;
    __syncthreads();
    float bs = 0.f;
    #pragma unroll
    for (int w = 0; w < 8; w++) bs += redS[w];
    wS[tid] = e * (1.0f / bs);
    __syncthreads();

    // ---- Weighted sum: out[e] = sum_t w_t * keys[t][e]  (keys from L2) ----
    {
        const int e_ = tid & 63;
        const int g  = tid >> 6;
        float acc = 0.f;
        for (int t = g; t < T_REAL; t += 4)
            acc += wS[t] * kg[t * E_DIM + e_];
        h1S[g * 64 + e_] = acc;            // h1S reused as scratch
    }
    __syncthreads();
    if (tid < 64)
        out[(size_t)b * E_DIM + tid] =
            h1S[tid] + h1S[64 + tid] + h1S[128 + tid] + h1S[192 + tid];
}

extern "C" void kernel_launch(void* const* d_in, const int* in_sizes, int n_in,
                              void* d_out, int out_size) {
    const float* query = (const float*)d_in[0];
    const float* keys  = (const float*)d_in[1];
    const int*   klen  = (const int*)  d_in[2];
    const float* W1    = (const float*)d_in[3];
    const float* b1    = (const float*)d_in[4];
    const float* W2    = (const float*)d_in[5];
    const float* b2    = (const float*)d_in[6];
    const float* W3    = (const float*)d_in[7];
    const float* b3    = (const float*)d_in[8];
    float* out = (float*)d_out;

    const int B = in_sizes[0] / E_DIM;                // query is (B,1,64)
    const size_t smem_bytes = (size_t)SMEM_FLOATS * sizeof(float);  // ~90.4 KB

    cudaFuncSetAttribute(asp_kernel,
                         cudaFuncAttributeMaxDynamicSharedMemorySize,
                         (int)smem_bytes);

    asp_kernel<<<B, NTHREADS, smem_bytes>>>(query, keys, klen,
                                            W1, b1, W2, b2, W3, b3, out);
}